// round 2
// baseline (speedup 1.0000x reference)
#include <cuda_runtime.h>
#include <math.h>

#define T_LEN        32768
#define B_SEG        8
#define H_HEADS      8
#define D_DIM        128
#define C_COLS       1024          // H*D
#define C4           256           // float4 columns per row
#define NBLK         256           // total blocks (all co-resident: 2/SM x 148)
#define ROWS_PER_BLK 128           // 32768 / 256
#define NMLP         32            // blocks that continue into the MLP phases

// ---------------- device scratch (zero-initialized at module load) -----------
__device__ float g_accum[B_SEG * C_COLS];   // segment sums; invariant: 0 at kernel entry
__device__ float g_h1[B_SEG * 1024];
__device__ float g_h2[B_SEG * 256];
__device__ float g_h3[B_SEG * 512];
__device__ unsigned          g_cnt[4];      // barrier arrival counters (self-resetting)
__device__ volatile unsigned g_gen[4];      // barrier generations (monotonic)

__device__ __forceinline__ float silu(float v) { return v / (1.0f + expf(-v)); }

// Software grid barrier. Releaser resets count and bumps generation; gen is
// monotonic across graph replays so no cross-launch reset hazard exists.
__device__ __forceinline__ void grid_bar(int id, unsigned target, bool wait)
{
    __syncthreads();
    if (threadIdx.x == 0) {
        __threadfence();                       // publish my block's writes
        unsigned gen = g_gen[id];
        if (atomicAdd(&g_cnt[id], 1u) == target - 1u) {
            g_cnt[id] = 0u;
            __threadfence();
            g_gen[id] = gen + 1u;
        } else if (wait) {
            while (g_gen[id] == gen) __nanosleep(64);
            __threadfence();                   // acquire
        }
    }
    __syncthreads();
}

// Shared memory reused across phases (max member = P2: 40960 B < 48 KB static)
union SmemU {
    int scu[B_SEG + 1];                                              // P0
    struct { float pooled[D_DIM * 8]; float inv_s[8]; } p1;          // P1
    struct { float xs[1024 * 8]; float red[16 * 16 * 8]; } p2;       // P2 (40 KB)
    struct { float xs[256 * 8];  float red[16 * 16 * 8]; } p3;       // P3
    struct { float x3[512]; float red[256]; float l0[128]; float l1[128]; } p4; // P4
};

__global__ void __launch_bounds__(256, 2) fused_kernel(
    const float4* __restrict__ x4, const int* __restrict__ cu,
    const float* __restrict__ w1, const float* __restrict__ b1,
    const float* __restrict__ w2, const float* __restrict__ b2,
    const float* __restrict__ w3, const float* __restrict__ b3,
    const float* __restrict__ w4, const float* __restrict__ b4,
    const float* __restrict__ w5, const float* __restrict__ b5,
    float* __restrict__ out)
{
    __shared__ SmemU sm;
    const int tid = threadIdx.x;
    const int blk = blockIdx.x;

    // ===================== P0: segment sum (all 256 blocks) ==================
    {
        const int t0 = blk * ROWS_PER_BLK;
        if (tid <= B_SEG) sm.scu[tid] = cu[tid];
        __syncthreads();

        const int t1 = t0 + ROWS_PER_BLK - 1;
        int s0 = 0; while (s0 < B_SEG - 1 && t0 >= sm.scu[s0 + 1]) s0++;
        int s1 = 0; while (s1 < B_SEG - 1 && t1 >= sm.scu[s1 + 1]) s1++;

        const float4* xp = x4 + (size_t)t0 * C4 + tid;

        if (s0 == s1) {
            float4 a = make_float4(0.f, 0.f, 0.f, 0.f);
            #pragma unroll 8
            for (int r = 0; r < ROWS_PER_BLK; r++) {
                float4 v = xp[r * C4];
                a.x += v.x; a.y += v.y; a.z += v.z; a.w += v.w;
            }
            float* dst = g_accum + s0 * C_COLS + tid * 4;
            atomicAdd(dst + 0, a.x); atomicAdd(dst + 1, a.y);
            atomicAdd(dst + 2, a.z); atomicAdd(dst + 3, a.w);
        } else {
            float4 a = make_float4(0.f, 0.f, 0.f, 0.f);
            int seg = s0;
            int nxt = (seg < B_SEG - 1) ? sm.scu[seg + 1] : 0x7fffffff;
            for (int r = 0; r < ROWS_PER_BLK; r++) {
                int t = t0 + r;
                if (t >= nxt) {
                    float* dst = g_accum + seg * C_COLS + tid * 4;
                    atomicAdd(dst + 0, a.x); atomicAdd(dst + 1, a.y);
                    atomicAdd(dst + 2, a.z); atomicAdd(dst + 3, a.w);
                    a = make_float4(0.f, 0.f, 0.f, 0.f);
                    while (seg < B_SEG - 1 && t >= sm.scu[seg + 1]) seg++;
                    nxt = (seg < B_SEG - 1) ? sm.scu[seg + 1] : 0x7fffffff;
                }
                float4 v = xp[r * C4];
                a.x += v.x; a.y += v.y; a.z += v.z; a.w += v.w;
            }
            float* dst = g_accum + seg * C_COLS + tid * 4;
            atomicAdd(dst + 0, a.x); atomicAdd(dst + 1, a.y);
            atomicAdd(dst + 2, a.z); atomicAdd(dst + 3, a.w);
        }
    }

    // barrier 0: all 256 arrive; only blocks < NMLP wait and continue
    grid_bar(0, NBLK, blk < NMLP);
    if (blk >= NMLP) return;

    // ===================== P1: pooled mean + layer1 + silu (blocks 0..3) =====
    if (blk < 4) {
        if (tid < B_SEG) {
            int cnt = cu[tid + 1] - cu[tid];
            if (cnt < 1) cnt = 1;
            sm.p1.inv_s[tid] = 1.0f / ((float)cnt * (float)H_HEADS);
        }
        __syncthreads();
        for (int i = tid; i < D_DIM * B_SEG; i += 256) {
            int k = i >> 3, b = i & 7;
            float s = 0.f;
            #pragma unroll
            for (int h = 0; h < H_HEADS; h++)
                s += __ldcg(&g_accum[b * C_COLS + h * D_DIM + k]);
            sm.p1.pooled[k * 8 + b] = s * sm.p1.inv_s[b];
        }
        __syncthreads();

        const int j = blk * 256 + tid;                 // j in [0, 1024)
        float acc[8];
        #pragma unroll
        for (int b = 0; b < 8; b++) acc[b] = b1[j];
        #pragma unroll 4
        for (int k = 0; k < D_DIM; k++) {
            float w = w1[k * 1024 + j];
            float4 p0 = *(const float4*)&sm.p1.pooled[k * 8];
            float4 p1 = *(const float4*)&sm.p1.pooled[k * 8 + 4];
            acc[0] += p0.x * w; acc[1] += p0.y * w;
            acc[2] += p0.z * w; acc[3] += p0.w * w;
            acc[4] += p1.x * w; acc[5] += p1.y * w;
            acc[6] += p1.z * w; acc[7] += p1.w * w;
        }
        #pragma unroll
        for (int b = 0; b < 8; b++)
            g_h1[b * 1024 + j] = silu(acc[b]);
    }
    grid_bar(1, NMLP, true);

    // ===================== P2: layer2 (K=1024 -> N=256), blocks 0..15 ========
    if (blk < 16) {
        for (int i = tid; i < 1024 * 8; i += 256) {
            int b = i >> 10, k = i & 1023;
            sm.p2.xs[k * 8 + b] = __ldcg(&g_h1[b * 1024 + k]);
        }
        __syncthreads();

        const int jj = tid >> 4, slice = tid & 15;
        const int j = blk * 16 + jj;
        float acc[8];
        #pragma unroll
        for (int b = 0; b < 8; b++) acc[b] = 0.f;
        const int k0 = slice * 64;
        #pragma unroll 4
        for (int k = k0; k < k0 + 64; k++) {
            float w = w2[k * 256 + j];
            float4 p0 = *(const float4*)&sm.p2.xs[k * 8];
            float4 p1 = *(const float4*)&sm.p2.xs[k * 8 + 4];
            acc[0] += p0.x * w; acc[1] += p0.y * w;
            acc[2] += p0.z * w; acc[3] += p0.w * w;
            acc[4] += p1.x * w; acc[5] += p1.y * w;
            acc[6] += p1.z * w; acc[7] += p1.w * w;
        }
        float* r = &sm.p2.red[(slice * 16 + jj) * 8];
        #pragma unroll
        for (int b = 0; b < 8; b++) r[b] = acc[b];
        __syncthreads();
        if (tid < 128) {
            int ojj = tid >> 3, b = tid & 7;
            float s = 0.f;
            #pragma unroll
            for (int sl = 0; sl < 16; sl++) s += sm.p2.red[(sl * 16 + ojj) * 8 + b];
            int oj = blk * 16 + ojj;
            g_h2[b * 256 + oj] = s + b2[oj];
        }
    }
    grid_bar(2, NMLP, true);

    // ===================== P3: layer3 + silu (K=256 -> N=512), blocks 0..31 ==
    {
        for (int i = tid; i < 256 * 8; i += 256) {
            int b = i >> 8, k = i & 255;
            sm.p3.xs[k * 8 + b] = __ldcg(&g_h2[b * 256 + k]);
        }
        __syncthreads();

        const int jj = tid >> 4, slice = tid & 15;
        const int j = blk * 16 + jj;
        float acc[8];
        #pragma unroll
        for (int b = 0; b < 8; b++) acc[b] = 0.f;
        const int k0 = slice * 16;
        #pragma unroll 4
        for (int k = k0; k < k0 + 16; k++) {
            float w = w3[k * 512 + j];
            float4 p0 = *(const float4*)&sm.p3.xs[k * 8];
            float4 p1 = *(const float4*)&sm.p3.xs[k * 8 + 4];
            acc[0] += p0.x * w; acc[1] += p0.y * w;
            acc[2] += p0.z * w; acc[3] += p0.w * w;
            acc[4] += p1.x * w; acc[5] += p1.y * w;
            acc[6] += p1.z * w; acc[7] += p1.w * w;
        }
        float* r = &sm.p3.red[(slice * 16 + jj) * 8];
        #pragma unroll
        for (int b = 0; b < 8; b++) r[b] = acc[b];
        __syncthreads();
        if (tid < 128) {
            int ojj = tid >> 3, b = tid & 7;
            float s = 0.f;
            #pragma unroll
            for (int sl = 0; sl < 16; sl++) s += sm.p3.red[(sl * 16 + ojj) * 8 + b];
            int oj = blk * 16 + ojj;
            g_h3[b * 512 + oj] = silu(s + b3[oj]);
        }
    }
    grid_bar(3, NMLP, blk < 8);
    if (blk >= 8) return;

    // ===================== P4: layer4+silu, layer5, argmax, out, reset =======
    {
        const int b = blk;
        for (int i = tid; i < 512; i += 256)
            sm.p4.x3[i] = __ldcg(&g_h3[b * 512 + i]);
        __syncthreads();

        const int jj = tid & 127, sl = tid >> 7;
        float acc = 0.f;
        const int k0 = sl * 256;
        #pragma unroll 4
        for (int k = k0; k < k0 + 256; k++)
            acc += sm.p4.x3[k] * w4[k * 128 + jj];
        sm.p4.red[sl * 128 + jj] = acc;
        __syncthreads();

        if (tid < 128) {
            float v = silu(sm.p4.red[tid] + sm.p4.red[128 + tid] + b4[tid]);
            sm.p4.l0[tid] = v * w5[tid * 2 + 0];
            sm.p4.l1[tid] = v * w5[tid * 2 + 1];
        }
        __syncthreads();
        #pragma unroll
        for (int stride = 64; stride > 0; stride >>= 1) {
            if (tid < stride) {
                sm.p4.l0[tid] += sm.p4.l0[tid + stride];
                sm.p4.l1[tid] += sm.p4.l1[tid + stride];
            }
            __syncthreads();
        }
        if (tid == 0) {
            float lg0 = sm.p4.l0[0] + b5[0];
            float lg1 = sm.p4.l1[0] + b5[1];
            float z = (lg1 > lg0) ? 1.0f : 0.0f;   // argmax; tie -> class 0
            #pragma unroll
            for (int h = 0; h < H_HEADS; h++)
                out[b * H_HEADS + h] = z;
        }
        // restore accumulator invariant for the next graph replay
        for (int i = tid; i < C_COLS; i += 256)
            g_accum[b * C_COLS + i] = 0.f;
    }
}

// ---------------- launch ------------------------------------------------------
extern "C" void kernel_launch(void* const* d_in, const int* in_sizes, int n_in,
                              void* d_out, int out_size)
{
    const float* x  = (const float*)d_in[0];
    const int*   cu = (const int*)  d_in[1];
    const float* w1 = (const float*)d_in[2];
    const float* b1 = (const float*)d_in[3];
    const float* w2 = (const float*)d_in[4];
    const float* b2 = (const float*)d_in[5];
    const float* w3 = (const float*)d_in[6];
    const float* b3 = (const float*)d_in[7];
    const float* w4 = (const float*)d_in[8];
    const float* b4 = (const float*)d_in[9];
    const float* w5 = (const float*)d_in[10];
    const float* b5 = (const float*)d_in[11];

    fused_kernel<<<NBLK, 256>>>((const float4*)x, cu,
                                w1, b1, w2, b2, w3, b3, w4, b4, w5, b5,
                                (float*)d_out);
}

// round 3
// speedup vs baseline: 2.3791x; 2.3791x over previous
#include <cuda_runtime.h>
#include <math.h>

#define T_LEN        32768
#define B_SEG        8
#define H_HEADS      8
#define D_DIM        128
#define C_COLS       1024          // H*D
#define C4           256           // float4 columns per row
#define RBLK         1024          // reduce blocks
#define ROWS_PER_BLK 32            // 32768 / 1024
#define NMLP         32            // MLP persistent blocks

// ---------------- device scratch (zero-initialized at module load) -----------
__device__ float g_accum[B_SEG * C_COLS];   // segment sums; invariant: 0 at entry
__device__ float g_h1[B_SEG * 1024];
__device__ float g_h2[B_SEG * 256];
__device__ float g_h3[B_SEG * 512];
__device__ unsigned          g_cnt[4];
__device__ volatile unsigned g_gen[4];

__device__ __forceinline__ float silu(float v) { return v / (1.0f + expf(-v)); }

// Grid barrier among NMLP blocks. Generation is monotonic across graph replays.
__device__ __forceinline__ void grid_bar(int id, unsigned target, bool wait)
{
    __syncthreads();
    if (threadIdx.x == 0) {
        __threadfence();
        unsigned gen = g_gen[id];
        if (atomicAdd(&g_cnt[id], 1u) == target - 1u) {
            g_cnt[id] = 0u;
            __threadfence();
            g_gen[id] = gen + 1u;
        } else if (wait) {
            while (g_gen[id] == gen) __nanosleep(32);
            __threadfence();
        }
    }
    __syncthreads();
}

// =================== K1: streaming segment-sum =================================
// 1024 blocks x 256 threads; block covers 32 rows; thread owns float4 column tid.
__global__ void __launch_bounds__(256) reduce_kernel(
    const float4* __restrict__ x4, const int* __restrict__ cu)
{
    const int tid = threadIdx.x;
    const int t0  = blockIdx.x * ROWS_PER_BLK;

    __shared__ int scu[B_SEG + 1];
    if (tid <= B_SEG) scu[tid] = cu[tid];
    __syncthreads();

    const int t1 = t0 + ROWS_PER_BLK - 1;
    int s0 = 0; while (s0 < B_SEG - 1 && t0 >= scu[s0 + 1]) s0++;
    int s1 = 0; while (s1 < B_SEG - 1 && t1 >= scu[s1 + 1]) s1++;

    const float4* xp = x4 + (size_t)t0 * C4 + tid;

    if (s0 == s1) {
        // fast path: 32 fully independent streaming loads, 4 accumulators
        float4 a0 = make_float4(0.f,0.f,0.f,0.f);
        float4 a1 = a0, a2 = a0, a3 = a0;
        #pragma unroll
        for (int r = 0; r < ROWS_PER_BLK; r += 4) {
            float4 v0 = __ldcs(&xp[(r + 0) * C4]);
            float4 v1 = __ldcs(&xp[(r + 1) * C4]);
            float4 v2 = __ldcs(&xp[(r + 2) * C4]);
            float4 v3 = __ldcs(&xp[(r + 3) * C4]);
            a0.x += v0.x; a0.y += v0.y; a0.z += v0.z; a0.w += v0.w;
            a1.x += v1.x; a1.y += v1.y; a1.z += v1.z; a1.w += v1.w;
            a2.x += v2.x; a2.y += v2.y; a2.z += v2.z; a2.w += v2.w;
            a3.x += v3.x; a3.y += v3.y; a3.z += v3.z; a3.w += v3.w;
        }
        a0.x += a1.x; a0.y += a1.y; a0.z += a1.z; a0.w += a1.w;
        a2.x += a3.x; a2.y += a3.y; a2.z += a3.z; a2.w += a3.w;
        a0.x += a2.x; a0.y += a2.y; a0.z += a2.z; a0.w += a2.w;
        float* dst = g_accum + s0 * C_COLS + tid * 4;
        atomicAdd(dst + 0, a0.x); atomicAdd(dst + 1, a0.y);
        atomicAdd(dst + 2, a0.z); atomicAdd(dst + 3, a0.w);
    } else {
        // slow path: segment boundary inside block (<=7 blocks of 1024)
        float4 a = make_float4(0.f,0.f,0.f,0.f);
        int seg = s0;
        int nxt = (seg < B_SEG - 1) ? scu[seg + 1] : 0x7fffffff;
        for (int r = 0; r < ROWS_PER_BLK; r++) {
            int t = t0 + r;
            if (t >= nxt) {
                float* dst = g_accum + seg * C_COLS + tid * 4;
                atomicAdd(dst + 0, a.x); atomicAdd(dst + 1, a.y);
                atomicAdd(dst + 2, a.z); atomicAdd(dst + 3, a.w);
                a = make_float4(0.f,0.f,0.f,0.f);
                while (seg < B_SEG - 1 && t >= scu[seg + 1]) seg++;
                nxt = (seg < B_SEG - 1) ? scu[seg + 1] : 0x7fffffff;
            }
            float4 v = __ldcs(&xp[r * C4]);
            a.x += v.x; a.y += v.y; a.z += v.z; a.w += v.w;
        }
        float* dst = g_accum + seg * C_COLS + tid * 4;
        atomicAdd(dst + 0, a.x); atomicAdd(dst + 1, a.y);
        atomicAdd(dst + 2, a.z); atomicAdd(dst + 3, a.w);
    }
}

// =================== K2: persistent MLP (32 blocks) ============================
union SmemU {
    struct { float pooled[D_DIM * 8]; float inv_s[8];
             float red[8 * 32 * 8]; } p1;                             // 12.2 KB
    struct { float xs[1024 * 8]; float red[32 * 8 * 8]; } p2;          // 40 KB
    struct { float xs[256 * 8];  float red[16 * 16 * 8]; } p3;         // 16 KB
    struct { float x3[512]; float red[256]; float l0[128]; float l1[128]; } p4;
};

__global__ void __launch_bounds__(256) mlp_kernel(
    const int* __restrict__ cu,
    const float* __restrict__ w1, const float* __restrict__ b1,
    const float* __restrict__ w2, const float* __restrict__ b2,
    const float* __restrict__ w3, const float* __restrict__ b3,
    const float* __restrict__ w4, const float* __restrict__ b4,
    const float* __restrict__ w5, const float* __restrict__ b5,
    float* __restrict__ out)
{
    __shared__ SmemU sm;
    const int tid = threadIdx.x;
    const int blk = blockIdx.x;

    // ---------- P1: pooled mean + layer1 + silu (all 32 blocks, 32 j each) ----
    {
        if (tid < B_SEG) {
            int cnt = cu[tid + 1] - cu[tid];
            if (cnt < 1) cnt = 1;
            sm.p1.inv_s[tid] = 1.0f / ((float)cnt * (float)H_HEADS);
        }
        __syncthreads();
        for (int i = tid; i < D_DIM * B_SEG; i += 256) {
            int k = i >> 3, b = i & 7;
            float s = 0.f;
            #pragma unroll
            for (int h = 0; h < H_HEADS; h++)
                s += __ldcg(&g_accum[b * C_COLS + h * D_DIM + k]);
            sm.p1.pooled[k * 8 + b] = s * sm.p1.inv_s[b];
        }
        __syncthreads();

        const int jj = tid & 31, slice = tid >> 5;       // 8 slices x 16 k
        const int j  = blk * 32 + jj;
        float acc[8];
        #pragma unroll
        for (int b = 0; b < 8; b++) acc[b] = 0.f;
        const int k0 = slice * 16;
        #pragma unroll 4
        for (int k = k0; k < k0 + 16; k++) {
            float w  = w1[k * 1024 + j];                 // lanes: consecutive j
            float4 p0 = *(const float4*)&sm.p1.pooled[k * 8];
            float4 p1 = *(const float4*)&sm.p1.pooled[k * 8 + 4];
            acc[0] += p0.x * w; acc[1] += p0.y * w;
            acc[2] += p0.z * w; acc[3] += p0.w * w;
            acc[4] += p1.x * w; acc[5] += p1.y * w;
            acc[6] += p1.z * w; acc[7] += p1.w * w;
        }
        float* r = &sm.p1.red[(slice * 32 + jj) * 8];
        #pragma unroll
        for (int b = 0; b < 8; b++) r[b] = acc[b];
        __syncthreads();

        const int ojj = tid >> 3, ob = tid & 7;          // 256 threads = 32 j x 8 b
        float s = 0.f;
        #pragma unroll
        for (int sl = 0; sl < 8; sl++)
            s += sm.p1.red[(sl * 32 + ojj) * 8 + ob];
        const int oj = blk * 32 + ojj;
        g_h1[ob * 1024 + oj] = silu(s + b1[oj]);
    }
    grid_bar(1, NMLP, true);

    // ---------- P2: layer2 K=1024 -> N=256 (32 blocks, 8 j each) --------------
    {
        for (int i = tid; i < 1024 * 8; i += 256) {
            int b = i >> 10, k = i & 1023;
            sm.p2.xs[k * 8 + b] = __ldcg(&g_h1[i]);
        }
        __syncthreads();

        const int jj = tid & 7, slice = tid >> 3;        // 32 slices x 32 k
        const int j  = blk * 8 + jj;
        float acc[8];
        #pragma unroll
        for (int b = 0; b < 8; b++) acc[b] = 0.f;
        const int k0 = slice * 32;
        #pragma unroll 4
        for (int k = k0; k < k0 + 32; k++) {
            float w  = w2[k * 256 + j];
            float4 p0 = *(const float4*)&sm.p2.xs[k * 8];
            float4 p1 = *(const float4*)&sm.p2.xs[k * 8 + 4];
            acc[0] += p0.x * w; acc[1] += p0.y * w;
            acc[2] += p0.z * w; acc[3] += p0.w * w;
            acc[4] += p1.x * w; acc[5] += p1.y * w;
            acc[6] += p1.z * w; acc[7] += p1.w * w;
        }
        float* r = &sm.p2.red[(slice * 8 + jj) * 8];
        #pragma unroll
        for (int b = 0; b < 8; b++) r[b] = acc[b];
        __syncthreads();

        if (tid < 64) {                                  // 8 j x 8 b
            const int ojj = tid >> 3, ob = tid & 7;
            float s = 0.f;
            #pragma unroll
            for (int sl = 0; sl < 32; sl++)
                s += sm.p2.red[(sl * 8 + ojj) * 8 + ob];
            const int oj = blk * 8 + ojj;
            g_h2[ob * 256 + oj] = s + b2[oj];            // no activation
        }
    }
    grid_bar(2, NMLP, true);

    // ---------- P3: layer3 + silu K=256 -> N=512 (32 blocks, 16 j each) -------
    {
        for (int i = tid; i < 256 * 8; i += 256) {
            int b = i >> 8, k = i & 255;
            sm.p3.xs[k * 8 + b] = __ldcg(&g_h2[i]);
        }
        __syncthreads();

        const int jj = tid & 15, slice = tid >> 4;       // 16 slices x 16 k
        const int j  = blk * 16 + jj;
        float acc[8];
        #pragma unroll
        for (int b = 0; b < 8; b++) acc[b] = 0.f;
        const int k0 = slice * 16;
        #pragma unroll 4
        for (int k = k0; k < k0 + 16; k++) {
            float w  = w3[k * 512 + j];
            float4 p0 = *(const float4*)&sm.p3.xs[k * 8];
            float4 p1 = *(const float4*)&sm.p3.xs[k * 8 + 4];
            acc[0] += p0.x * w; acc[1] += p0.y * w;
            acc[2] += p0.z * w; acc[3] += p0.w * w;
            acc[4] += p1.x * w; acc[5] += p1.y * w;
            acc[6] += p1.z * w; acc[7] += p1.w * w;
        }
        float* r = &sm.p3.red[(slice * 16 + jj) * 8];
        #pragma unroll
        for (int b = 0; b < 8; b++) r[b] = acc[b];
        __syncthreads();

        if (tid < 128) {                                 // 16 j x 8 b
            const int ojj = tid >> 3, ob = tid & 7;
            float s = 0.f;
            #pragma unroll
            for (int sl = 0; sl < 16; sl++)
                s += sm.p3.red[(sl * 16 + ojj) * 8 + ob];
            const int oj = blk * 16 + ojj;
            g_h3[ob * 512 + oj] = silu(s + b3[oj]);
        }
    }
    grid_bar(3, NMLP, blk < 8);
    if (blk >= 8) return;

    // ---------- P4: layer4+silu, layer5, argmax, output, accum reset ----------
    {
        const int b = blk;
        for (int i = tid; i < 512; i += 256)
            sm.p4.x3[i] = __ldcg(&g_h3[b * 512 + i]);
        __syncthreads();

        const int jj = tid & 127, sl = tid >> 7;
        float acc = 0.f;
        const int k0 = sl * 256;
        #pragma unroll 4
        for (int k = k0; k < k0 + 256; k++)
            acc += sm.p4.x3[k] * w4[k * 128 + jj];       // lanes: consecutive jj
        sm.p4.red[sl * 128 + jj] = acc;
        __syncthreads();

        if (tid < 128) {
            float v = silu(sm.p4.red[tid] + sm.p4.red[128 + tid] + b4[tid]);
            sm.p4.l0[tid] = v * w5[tid * 2 + 0];
            sm.p4.l1[tid] = v * w5[tid * 2 + 1];
        }
        __syncthreads();
        #pragma unroll
        for (int stride = 64; stride > 0; stride >>= 1) {
            if (tid < stride) {
                sm.p4.l0[tid] += sm.p4.l0[tid + stride];
                sm.p4.l1[tid] += sm.p4.l1[tid + stride];
            }
            __syncthreads();
        }
        if (tid == 0) {
            float lg0 = sm.p4.l0[0] + b5[0];
            float lg1 = sm.p4.l1[0] + b5[1];
            float z = (lg1 > lg0) ? 1.0f : 0.0f;
            #pragma unroll
            for (int h = 0; h < H_HEADS; h++)
                out[b * H_HEADS + h] = z;
        }
        for (int i = tid; i < C_COLS; i += 256)
            g_accum[b * C_COLS + i] = 0.f;               // restore invariant
    }
}

// ---------------- launch ------------------------------------------------------
extern "C" void kernel_launch(void* const* d_in, const int* in_sizes, int n_in,
                              void* d_out, int out_size)
{
    const float* x  = (const float*)d_in[0];
    const int*   cu = (const int*)  d_in[1];
    const float* w1 = (const float*)d_in[2];
    const float* b1 = (const float*)d_in[3];
    const float* w2 = (const float*)d_in[4];
    const float* b2 = (const float*)d_in[5];
    const float* w3 = (const float*)d_in[6];
    const float* b3 = (const float*)d_in[7];
    const float* w4 = (const float*)d_in[8];
    const float* b4 = (const float*)d_in[9];
    const float* w5 = (const float*)d_in[10];
    const float* b5 = (const float*)d_in[11];

    reduce_kernel<<<RBLK, 256>>>((const float4*)x, cu);
    mlp_kernel<<<NMLP, 256>>>(cu, w1, b1, w2, b2, w3, b3, w4, b4, w5, b5,
                              (float*)d_out);
}

// round 4
// speedup vs baseline: 2.5439x; 1.0693x over previous
#include <cuda_runtime.h>
#include <math.h>

#define T_LEN        32768
#define B_SEG        8
#define H_HEADS      8
#define D_DIM        128
#define C_COLS       1024
#define C4           256
#define RBLK         1024
#define ROWS_PER_BLK 32
#define NMLP         32

// ---------------- device scratch (zero-initialized at module load) -----------
__device__ float g_accum[B_SEG * C_COLS];   // segment sums; invariant: 0 at entry
__device__ float g_h1[B_SEG * 1024];
__device__ float g_h2[B_SEG * 256];         // preloaded with bias, then atomic partials
__device__ float g_h3[B_SEG * 512];
__device__ unsigned          g_cnt[4];
__device__ volatile unsigned g_gen[4];

__device__ __forceinline__ float silu(float v) { return v / (1.0f + expf(-v)); }

__device__ __forceinline__ void grid_bar(int id, unsigned target, bool wait)
{
    __syncthreads();
    if (threadIdx.x == 0) {
        __threadfence();
        unsigned gen = g_gen[id];
        if (atomicAdd(&g_cnt[id], 1u) == target - 1u) {
            g_cnt[id] = 0u;
            __threadfence();
            g_gen[id] = gen + 1u;
        } else if (wait) {
            while (g_gen[id] == gen) __nanosleep(32);
            __threadfence();
        }
    }
    __syncthreads();
}

// =================== K1: streaming segment-sum (unchanged) ====================
__global__ void __launch_bounds__(256) reduce_kernel(
    const float4* __restrict__ x4, const int* __restrict__ cu)
{
    const int tid = threadIdx.x;
    const int t0  = blockIdx.x * ROWS_PER_BLK;

    __shared__ int scu[B_SEG + 1];
    if (tid <= B_SEG) scu[tid] = cu[tid];
    __syncthreads();

    const int t1 = t0 + ROWS_PER_BLK - 1;
    int s0 = 0; while (s0 < B_SEG - 1 && t0 >= scu[s0 + 1]) s0++;
    int s1 = 0; while (s1 < B_SEG - 1 && t1 >= scu[s1 + 1]) s1++;

    const float4* xp = x4 + (size_t)t0 * C4 + tid;

    if (s0 == s1) {
        float4 a0 = make_float4(0.f,0.f,0.f,0.f);
        float4 a1 = a0, a2 = a0, a3 = a0;
        #pragma unroll
        for (int r = 0; r < ROWS_PER_BLK; r += 4) {
            float4 v0 = __ldcs(&xp[(r + 0) * C4]);
            float4 v1 = __ldcs(&xp[(r + 1) * C4]);
            float4 v2 = __ldcs(&xp[(r + 2) * C4]);
            float4 v3 = __ldcs(&xp[(r + 3) * C4]);
            a0.x += v0.x; a0.y += v0.y; a0.z += v0.z; a0.w += v0.w;
            a1.x += v1.x; a1.y += v1.y; a1.z += v1.z; a1.w += v1.w;
            a2.x += v2.x; a2.y += v2.y; a2.z += v2.z; a2.w += v2.w;
            a3.x += v3.x; a3.y += v3.y; a3.z += v3.z; a3.w += v3.w;
        }
        a0.x += a1.x; a0.y += a1.y; a0.z += a1.z; a0.w += a1.w;
        a2.x += a3.x; a2.y += a3.y; a2.z += a3.z; a2.w += a3.w;
        a0.x += a2.x; a0.y += a2.y; a0.z += a2.z; a0.w += a2.w;
        float* dst = g_accum + s0 * C_COLS + tid * 4;
        atomicAdd(dst + 0, a0.x); atomicAdd(dst + 1, a0.y);
        atomicAdd(dst + 2, a0.z); atomicAdd(dst + 3, a0.w);
    } else {
        float4 a = make_float4(0.f,0.f,0.f,0.f);
        int seg = s0;
        int nxt = (seg < B_SEG - 1) ? scu[seg + 1] : 0x7fffffff;
        for (int r = 0; r < ROWS_PER_BLK; r++) {
            int t = t0 + r;
            if (t >= nxt) {
                float* dst = g_accum + seg * C_COLS + tid * 4;
                atomicAdd(dst + 0, a.x); atomicAdd(dst + 1, a.y);
                atomicAdd(dst + 2, a.z); atomicAdd(dst + 3, a.w);
                a = make_float4(0.f,0.f,0.f,0.f);
                while (seg < B_SEG - 1 && t >= scu[seg + 1]) seg++;
                nxt = (seg < B_SEG - 1) ? scu[seg + 1] : 0x7fffffff;
            }
            float4 v = __ldcs(&xp[r * C4]);
            a.x += v.x; a.y += v.y; a.z += v.z; a.w += v.w;
        }
        float* dst = g_accum + seg * C_COLS + tid * 4;
        atomicAdd(dst + 0, a.x); atomicAdd(dst + 1, a.y);
        atomicAdd(dst + 2, a.z); atomicAdd(dst + 3, a.w);
    }
}

// =================== K2: persistent MLP, latency-batched weight loads =========
union SmemU {
    struct { float inv[8]; float pooled[1024]; float4 red[2048]; } p1;  // ~37 KB
    struct { float xs[512];  float4 red[2048]; } p2;                    // 34 KB
    struct { float xs[2048]; float4 red[2048]; } p3;                    // 40 KB
    struct { float x3[512]; float4 red[256]; float h4[128];
             float l0[128]; float l1[128]; } p4;
};

__global__ void __launch_bounds__(256) mlp_kernel(
    const int* __restrict__ cu,
    const float* __restrict__ w1, const float* __restrict__ b1,
    const float* __restrict__ w2, const float* __restrict__ b2,
    const float* __restrict__ w3, const float* __restrict__ b3,
    const float* __restrict__ w4, const float* __restrict__ b4,
    const float* __restrict__ w5, const float* __restrict__ b5,
    float* __restrict__ out)
{
    __shared__ SmemU sm;
    const int tid  = threadIdx.x;
    const int blk  = blockIdx.x;
    const int lane = tid & 31;
    const int ksl  = tid >> 5;

    // ========== P1: pooled mean + layer1 (8 blocks), bias preload (block 8) ===
    if (blk < 8) {
        if (tid < B_SEG) {
            int cnt = cu[tid + 1] - cu[tid];
            if (cnt < 1) cnt = 1;
            sm.p1.inv[tid] = 1.0f / ((float)cnt * (float)H_HEADS);
        }
        __syncthreads();
        for (int i = tid; i < 1024; i += 256) {
            int k = i >> 3, b = i & 7;
            float s = 0.f;
            #pragma unroll
            for (int h = 0; h < H_HEADS; h++)
                s += __ldcg(&g_accum[b * C_COLS + h * D_DIM + k]);
            sm.p1.pooled[k * 8 + b] = s * sm.p1.inv[b];
        }
        __syncthreads();

        const int j0 = blk * 128 + lane * 4;
        float4 acc[8];
        #pragma unroll
        for (int b = 0; b < 8; b++) acc[b] = make_float4(0.f,0.f,0.f,0.f);
        const int kbeg = ksl * 16;
        #pragma unroll
        for (int kk = 0; kk < 16; kk++) {
            int k = kbeg + kk;
            float4 w = *(const float4*)&w1[k * 1024 + j0];   // LDG.128, coalesced
            const float* xr = &sm.p1.pooled[k * 8];
            #pragma unroll
            for (int b = 0; b < 8; b++) {
                float xv = xr[b];
                acc[b].x += xv * w.x; acc[b].y += xv * w.y;
                acc[b].z += xv * w.z; acc[b].w += xv * w.w;
            }
        }
        #pragma unroll
        for (int b = 0; b < 8; b++)
            sm.p1.red[(ksl * 32 + lane) * 8 + b] = acc[b];
        __syncthreads();

        const int l = tid >> 3, b = tid & 7;                 // 32 j4 x 8 b
        float4 s = make_float4(0.f,0.f,0.f,0.f);
        #pragma unroll
        for (int sl = 0; sl < 8; sl++) {
            float4 v = sm.p1.red[(sl * 32 + l) * 8 + b];
            s.x += v.x; s.y += v.y; s.z += v.z; s.w += v.w;
        }
        float4 bias = *(const float4*)&b1[blk * 128 + l * 4];
        s.x = silu(s.x + bias.x); s.y = silu(s.y + bias.y);
        s.z = silu(s.z + bias.z); s.w = silu(s.w + bias.w);
        *(float4*)&g_h1[b * 1024 + blk * 128 + l * 4] = s;
    } else if (blk == 8) {
        // preload layer2 output with its bias (layer2 uses atomic accumulation)
        for (int i = tid; i < 2048; i += 256)
            g_h2[i] = b2[i & 255];
    }
    grid_bar(1, NMLP, true);

    // ========== P2: layer2 K=1024 -> N=256, all 32 blocks, atomic partials ====
    {
        const int jg = blk & 1, kb = blk >> 1;
        const int kbase = kb * 64;
        for (int i = tid; i < 512; i += 256) {
            int kk = i >> 3, b = i & 7;
            sm.p2.xs[kk * 8 + b] = __ldcg(&g_h1[b * 1024 + kbase + kk]);
        }
        __syncthreads();

        const int j0 = jg * 128 + lane * 4;
        float4 acc[8];
        #pragma unroll
        for (int b = 0; b < 8; b++) acc[b] = make_float4(0.f,0.f,0.f,0.f);
        const int klbeg = ksl * 8;
        #pragma unroll
        for (int kk = 0; kk < 8; kk++) {
            int kl = klbeg + kk;
            float4 w = *(const float4*)&w2[(kbase + kl) * 256 + j0];
            const float* xr = &sm.p2.xs[kl * 8];
            #pragma unroll
            for (int b = 0; b < 8; b++) {
                float xv = xr[b];
                acc[b].x += xv * w.x; acc[b].y += xv * w.y;
                acc[b].z += xv * w.z; acc[b].w += xv * w.w;
            }
        }
        #pragma unroll
        for (int b = 0; b < 8; b++)
            sm.p2.red[(ksl * 32 + lane) * 8 + b] = acc[b];
        __syncthreads();

        const int l = tid >> 3, b = tid & 7;
        float4 s = make_float4(0.f,0.f,0.f,0.f);
        #pragma unroll
        for (int sl = 0; sl < 8; sl++) {
            float4 v = sm.p2.red[(sl * 32 + l) * 8 + b];
            s.x += v.x; s.y += v.y; s.z += v.z; s.w += v.w;
        }
        float* dst = &g_h2[b * 256 + jg * 128 + l * 4];
        atomicAdd(dst + 0, s.x); atomicAdd(dst + 1, s.y);
        atomicAdd(dst + 2, s.z); atomicAdd(dst + 3, s.w);
    }
    grid_bar(2, NMLP, blk < 4);

    // ========== P3: layer3 + silu K=256 -> N=512 (4 blocks) ====================
    if (blk < 4) {
        for (int i = tid; i < 2048; i += 256) {
            int k = i >> 3, b = i & 7;
            sm.p3.xs[k * 8 + b] = __ldcg(&g_h2[b * 256 + k]);
        }
        __syncthreads();

        const int j0 = blk * 128 + lane * 4;
        float4 acc[8];
        #pragma unroll
        for (int b = 0; b < 8; b++) acc[b] = make_float4(0.f,0.f,0.f,0.f);
        const int kbeg = ksl * 32;
        #pragma unroll
        for (int kk = 0; kk < 32; kk++) {
            int k = kbeg + kk;
            float4 w = *(const float4*)&w3[k * 512 + j0];
            const float* xr = &sm.p3.xs[k * 8];
            #pragma unroll
            for (int b = 0; b < 8; b++) {
                float xv = xr[b];
                acc[b].x += xv * w.x; acc[b].y += xv * w.y;
                acc[b].z += xv * w.z; acc[b].w += xv * w.w;
            }
        }
        #pragma unroll
        for (int b = 0; b < 8; b++)
            sm.p3.red[(ksl * 32 + lane) * 8 + b] = acc[b];
        __syncthreads();

        const int l = tid >> 3, b = tid & 7;
        float4 s = make_float4(0.f,0.f,0.f,0.f);
        #pragma unroll
        for (int sl = 0; sl < 8; sl++) {
            float4 v = sm.p3.red[(sl * 32 + l) * 8 + b];
            s.x += v.x; s.y += v.y; s.z += v.z; s.w += v.w;
        }
        float4 bias = *(const float4*)&b3[blk * 128 + l * 4];
        s.x = silu(s.x + bias.x); s.y = silu(s.y + bias.y);
        s.z = silu(s.z + bias.z); s.w = silu(s.w + bias.w);
        *(float4*)&g_h3[b * 512 + blk * 128 + l * 4] = s;
    }
    grid_bar(3, NMLP, blk < 8);
    if (blk >= 8) return;

    // ========== P4: layer4+silu, layer5, argmax, out, accum reset (8 blocks) ==
    {
        const int b = blk;
        for (int i = tid; i < 512; i += 256)
            sm.p4.x3[i] = __ldcg(&g_h3[b * 512 + i]);
        __syncthreads();

        const int j0 = lane * 4;
        const int kbeg = ksl * 64;
        float4 acc = make_float4(0.f,0.f,0.f,0.f);
        #pragma unroll
        for (int kk = 0; kk < 64; kk++) {
            int k = kbeg + kk;
            float4 w = *(const float4*)&w4[k * 128 + j0];    // 64 indep LDG.128
            float xv = sm.p4.x3[k];
            acc.x += xv * w.x; acc.y += xv * w.y;
            acc.z += xv * w.z; acc.w += xv * w.w;
        }
        sm.p4.red[ksl * 32 + lane] = acc;
        __syncthreads();

        if (tid < 32) {
            float4 s = make_float4(0.f,0.f,0.f,0.f);
            #pragma unroll
            for (int sl = 0; sl < 8; sl++) {
                float4 v = sm.p4.red[sl * 32 + tid];
                s.x += v.x; s.y += v.y; s.z += v.z; s.w += v.w;
            }
            float4 bias = *(const float4*)&b4[tid * 4];
            sm.p4.h4[tid * 4 + 0] = silu(s.x + bias.x);
            sm.p4.h4[tid * 4 + 1] = silu(s.y + bias.y);
            sm.p4.h4[tid * 4 + 2] = silu(s.z + bias.z);
            sm.p4.h4[tid * 4 + 3] = silu(s.w + bias.w);
        }
        __syncthreads();

        if (tid < 128) {
            float v = sm.p4.h4[tid];
            sm.p4.l0[tid] = v * w5[tid * 2 + 0];
            sm.p4.l1[tid] = v * w5[tid * 2 + 1];
        }
        __syncthreads();
        #pragma unroll
        for (int stride = 64; stride > 0; stride >>= 1) {
            if (tid < stride) {
                sm.p4.l0[tid] += sm.p4.l0[tid + stride];
                sm.p4.l1[tid] += sm.p4.l1[tid + stride];
            }
            __syncthreads();
        }
        if (tid == 0) {
            float lg0 = sm.p4.l0[0] + b5[0];
            float lg1 = sm.p4.l1[0] + b5[1];
            float z = (lg1 > lg0) ? 1.0f : 0.0f;            // argmax; tie -> 0
            #pragma unroll
            for (int h = 0; h < H_HEADS; h++)
                out[b * H_HEADS + h] = z;
        }
        for (int i = tid; i < C_COLS; i += 256)
            g_accum[b * C_COLS + i] = 0.f;                  // restore invariant
    }
}

// ---------------- launch ------------------------------------------------------
extern "C" void kernel_launch(void* const* d_in, const int* in_sizes, int n_in,
                              void* d_out, int out_size)
{
    const float* x  = (const float*)d_in[0];
    const int*   cu = (const int*)  d_in[1];
    const float* w1 = (const float*)d_in[2];
    const float* b1 = (const float*)d_in[3];
    const float* w2 = (const float*)d_in[4];
    const float* b2 = (const float*)d_in[5];
    const float* w3 = (const float*)d_in[6];
    const float* b3 = (const float*)d_in[7];
    const float* w4 = (const float*)d_in[8];
    const float* b4 = (const float*)d_in[9];
    const float* w5 = (const float*)d_in[10];
    const float* b5 = (const float*)d_in[11];

    reduce_kernel<<<RBLK, 256>>>((const float4*)x, cu);
    mlp_kernel<<<NMLP, 256>>>(cu, w1, b1, w2, b2, w3, b3, w4, b4, w5, b5,
                              (float*)d_out);
}

// round 5
// speedup vs baseline: 2.8068x; 1.1033x over previous
#include <cuda_runtime.h>
#include <math.h>

#define T_LEN        32768
#define B_SEG        8
#define H_HEADS      8
#define D_DIM        128
#define C_COLS       1024
#define C4           256
#define RBLK         1024
#define ROWS_PER_BLK 32

// ---------------- device scratch (zero-initialized at module load) -----------
__device__ float g_accum[B_SEG * C_COLS];   // segment sums; invariant: 0 at entry

__device__ __forceinline__ float silu(float v) { return v / (1.0f + expf(-v)); }

// =================== K1: streaming segment-sum ================================
// 1024 blocks x 256 threads; block covers 32 rows; thread owns float4 column tid.
__global__ void __launch_bounds__(256) reduce_kernel(
    const float4* __restrict__ x4, const int* __restrict__ cu)
{
    const int tid = threadIdx.x;
    const int t0  = blockIdx.x * ROWS_PER_BLK;

    __shared__ int scu[B_SEG + 1];
    if (tid <= B_SEG) scu[tid] = cu[tid];
    __syncthreads();

    const int t1 = t0 + ROWS_PER_BLK - 1;
    int s0 = 0; while (s0 < B_SEG - 1 && t0 >= scu[s0 + 1]) s0++;
    int s1 = 0; while (s1 < B_SEG - 1 && t1 >= scu[s1 + 1]) s1++;

    const float4* xp = x4 + (size_t)t0 * C4 + tid;

    if (s0 == s1) {
        // 8 independent accumulators, 8 loads in flight per iteration
        float4 a[8];
        #pragma unroll
        for (int i = 0; i < 8; i++) a[i] = make_float4(0.f,0.f,0.f,0.f);
        #pragma unroll
        for (int r = 0; r < ROWS_PER_BLK; r += 8) {
            #pragma unroll
            for (int u = 0; u < 8; u++) {
                float4 v = __ldcs(&xp[(r + u) * C4]);
                a[u].x += v.x; a[u].y += v.y; a[u].z += v.z; a[u].w += v.w;
            }
        }
        #pragma unroll
        for (int s = 4; s > 0; s >>= 1)
            #pragma unroll
            for (int i = 0; i < s; i++) {
                a[i].x += a[i+s].x; a[i].y += a[i+s].y;
                a[i].z += a[i+s].z; a[i].w += a[i+s].w;
            }
        float* dst = g_accum + s0 * C_COLS + tid * 4;
        atomicAdd(dst + 0, a[0].x); atomicAdd(dst + 1, a[0].y);
        atomicAdd(dst + 2, a[0].z); atomicAdd(dst + 3, a[0].w);
    } else {
        float4 a = make_float4(0.f,0.f,0.f,0.f);
        int seg = s0;
        int nxt = (seg < B_SEG - 1) ? scu[seg + 1] : 0x7fffffff;
        for (int r = 0; r < ROWS_PER_BLK; r++) {
            int t = t0 + r;
            if (t >= nxt) {
                float* dst = g_accum + seg * C_COLS + tid * 4;
                atomicAdd(dst + 0, a.x); atomicAdd(dst + 1, a.y);
                atomicAdd(dst + 2, a.z); atomicAdd(dst + 3, a.w);
                a = make_float4(0.f,0.f,0.f,0.f);
                while (seg < B_SEG - 1 && t >= scu[seg + 1]) seg++;
                nxt = (seg < B_SEG - 1) ? scu[seg + 1] : 0x7fffffff;
            }
            float4 v = __ldcs(&xp[r * C4]);
            a.x += v.x; a.y += v.y; a.z += v.z; a.w += v.w;
        }
        float* dst = g_accum + seg * C_COLS + tid * 4;
        atomicAdd(dst + 0, a.x); atomicAdd(dst + 1, a.y);
        atomicAdd(dst + 2, a.z); atomicAdd(dst + 3, a.w);
    }
}

// =================== K2: whole MLP, one block per batch row ===================
// 8 blocks x 512 threads. All inter-layer sync is __syncthreads(); all
// activations live in shared memory. Weight reads are coalesced LDG.128.
__global__ void __launch_bounds__(512) mlp_kernel(
    const int* __restrict__ cu,
    const float* __restrict__ w1, const float* __restrict__ b1,
    const float* __restrict__ w2, const float* __restrict__ b2,
    const float* __restrict__ w3, const float* __restrict__ b3,
    const float* __restrict__ w4, const float* __restrict__ b4,
    const float* __restrict__ w5, const float* __restrict__ b5,
    float* __restrict__ out)
{
    __shared__ float  pooled[D_DIM];
    __shared__ float  h1[1024];
    __shared__ float  h2[256];
    __shared__ float  h3[512];
    __shared__ float  h4[128];
    __shared__ float4 red[512];          // 8 KB: per-layer k-slice partials
    __shared__ float  l0[128], l1[128];

    const int tid = threadIdx.x;
    const int b   = blockIdx.x;

    // ---- pooled mean over heads -------------------------------------------
    if (tid < D_DIM) {
        float s = 0.f;
        #pragma unroll
        for (int h = 0; h < H_HEADS; h++)
            s += __ldcg(&g_accum[b * C_COLS + h * D_DIM + tid]);
        int cnt = cu[b + 1] - cu[b];
        if (cnt < 1) cnt = 1;
        pooled[tid] = s / ((float)cnt * (float)H_HEADS);
    }
    __syncthreads();

    // ---- L1: 128 -> 1024, silu.  jq = tid&255 (j4), slice = tid>>8 (2 x 64k)
    {
        const int jq = tid & 255, slice = tid >> 8;
        const int k0 = slice * 64;
        float4 acc = make_float4(0.f,0.f,0.f,0.f);
        #pragma unroll 16
        for (int kk = 0; kk < 64; kk++) {
            float4 w = *(const float4*)&w1[(k0 + kk) * 1024 + jq * 4];
            float xv = pooled[k0 + kk];
            acc.x += xv * w.x; acc.y += xv * w.y;
            acc.z += xv * w.z; acc.w += xv * w.w;
        }
        red[slice * 256 + jq] = acc;
        __syncthreads();
        if (tid < 256) {
            float4 s0 = red[tid], s1 = red[256 + tid];
            float4 bias = *(const float4*)&b1[tid * 4];
            h1[tid * 4 + 0] = silu(s0.x + s1.x + bias.x);
            h1[tid * 4 + 1] = silu(s0.y + s1.y + bias.y);
            h1[tid * 4 + 2] = silu(s0.z + s1.z + bias.z);
            h1[tid * 4 + 3] = silu(s0.w + s1.w + bias.w);
        }
        __syncthreads();
    }

    // ---- L2: 1024 -> 256, no act.  jq = tid&63, slice = tid>>6 (8 x 128k) ---
    {
        const int jq = tid & 63, slice = tid >> 6;
        const int k0 = slice * 128;
        float4 acc = make_float4(0.f,0.f,0.f,0.f);
        #pragma unroll 16
        for (int kk = 0; kk < 128; kk++) {
            float4 w = *(const float4*)&w2[(k0 + kk) * 256 + jq * 4];
            float xv = h1[k0 + kk];
            acc.x += xv * w.x; acc.y += xv * w.y;
            acc.z += xv * w.z; acc.w += xv * w.w;
        }
        red[slice * 64 + jq] = acc;
        __syncthreads();
        if (tid < 64) {
            float4 s = make_float4(0.f,0.f,0.f,0.f);
            #pragma unroll
            for (int sl = 0; sl < 8; sl++) {
                float4 v = red[sl * 64 + tid];
                s.x += v.x; s.y += v.y; s.z += v.z; s.w += v.w;
            }
            float4 bias = *(const float4*)&b2[tid * 4];
            h2[tid * 4 + 0] = s.x + bias.x;
            h2[tid * 4 + 1] = s.y + bias.y;
            h2[tid * 4 + 2] = s.z + bias.z;
            h2[tid * 4 + 3] = s.w + bias.w;
        }
        __syncthreads();
    }

    // ---- L3: 256 -> 512, silu.  jq = tid&127, slice = tid>>7 (4 x 64k) ------
    {
        const int jq = tid & 127, slice = tid >> 7;
        const int k0 = slice * 64;
        float4 acc = make_float4(0.f,0.f,0.f,0.f);
        #pragma unroll 16
        for (int kk = 0; kk < 64; kk++) {
            float4 w = *(const float4*)&w3[(k0 + kk) * 512 + jq * 4];
            float xv = h2[k0 + kk];
            acc.x += xv * w.x; acc.y += xv * w.y;
            acc.z += xv * w.z; acc.w += xv * w.w;
        }
        red[slice * 128 + jq] = acc;
        __syncthreads();
        if (tid < 128) {
            float4 s = make_float4(0.f,0.f,0.f,0.f);
            #pragma unroll
            for (int sl = 0; sl < 4; sl++) {
                float4 v = red[sl * 128 + tid];
                s.x += v.x; s.y += v.y; s.z += v.z; s.w += v.w;
            }
            float4 bias = *(const float4*)&b3[tid * 4];
            h3[tid * 4 + 0] = silu(s.x + bias.x);
            h3[tid * 4 + 1] = silu(s.y + bias.y);
            h3[tid * 4 + 2] = silu(s.z + bias.z);
            h3[tid * 4 + 3] = silu(s.w + bias.w);
        }
        __syncthreads();
    }

    // ---- L4: 512 -> 128, silu.  jq = tid&31, slice = tid>>5 (16 x 32k) ------
    {
        const int jq = tid & 31, slice = tid >> 5;
        const int k0 = slice * 32;
        float4 acc = make_float4(0.f,0.f,0.f,0.f);
        #pragma unroll 16
        for (int kk = 0; kk < 32; kk++) {
            float4 w = *(const float4*)&w4[(k0 + kk) * 128 + jq * 4];
            float xv = h3[k0 + kk];
            acc.x += xv * w.x; acc.y += xv * w.y;
            acc.z += xv * w.z; acc.w += xv * w.w;
        }
        red[slice * 32 + jq] = acc;
        __syncthreads();
        if (tid < 32) {
            float4 s = make_float4(0.f,0.f,0.f,0.f);
            #pragma unroll
            for (int sl = 0; sl < 16; sl++) {
                float4 v = red[sl * 32 + tid];
                s.x += v.x; s.y += v.y; s.z += v.z; s.w += v.w;
            }
            float4 bias = *(const float4*)&b4[tid * 4];
            h4[tid * 4 + 0] = silu(s.x + bias.x);
            h4[tid * 4 + 1] = silu(s.y + bias.y);
            h4[tid * 4 + 2] = silu(s.z + bias.z);
            h4[tid * 4 + 3] = silu(s.w + bias.w);
        }
        __syncthreads();
    }

    // ---- L5: 128 -> 2, argmax, output ---------------------------------------
    if (tid < 128) {
        float v = h4[tid];
        l0[tid] = v * w5[tid * 2 + 0];
        l1[tid] = v * w5[tid * 2 + 1];
    }
    __syncthreads();
    #pragma unroll
    for (int stride = 64; stride > 0; stride >>= 1) {
        if (tid < stride) {
            l0[tid] += l0[tid + stride];
            l1[tid] += l1[tid + stride];
        }
        __syncthreads();
    }
    if (tid == 0) {
        float lg0 = l0[0] + b5[0];
        float lg1 = l1[0] + b5[1];
        float z = (lg1 > lg0) ? 1.0f : 0.0f;     // argmax; tie -> class 0
        #pragma unroll
        for (int h = 0; h < H_HEADS; h++)
            out[b * H_HEADS + h] = z;
    }

    // ---- restore accumulator invariant for next graph replay ----------------
    for (int i = tid; i < C_COLS; i += 512)
        g_accum[b * C_COLS + i] = 0.f;
}

// ---------------- launch ------------------------------------------------------
extern "C" void kernel_launch(void* const* d_in, const int* in_sizes, int n_in,
                              void* d_out, int out_size)
{
    const float* x  = (const float*)d_in[0];
    const int*   cu = (const int*)  d_in[1];
    const float* w1 = (const float*)d_in[2];
    const float* b1 = (const float*)d_in[3];
    const float* w2 = (const float*)d_in[4];
    const float* b2 = (const float*)d_in[5];
    const float* w3 = (const float*)d_in[6];
    const float* b3 = (const float*)d_in[7];
    const float* w4 = (const float*)d_in[8];
    const float* b4 = (const float*)d_in[9];
    const float* w5 = (const float*)d_in[10];
    const float* b5 = (const float*)d_in[11];

    reduce_kernel<<<RBLK, 256>>>((const float4*)x, cu);
    mlp_kernel<<<B_SEG, 512>>>(cu, w1, b1, w2, b2, w3, b3, w4, b4, w5, b5,
                               (float*)d_out);
}

// round 6
// speedup vs baseline: 3.1042x; 1.1060x over previous
#include <cuda_runtime.h>
#include <math.h>

#define T_LEN        32768
#define B_SEG        8
#define H_HEADS      8
#define D_DIM        128
#define C_COLS       1024
#define C4           256
#define RBLK         1024
#define ROWS_PER_BLK 32

__device__ float g_accum[B_SEG * C_COLS];   // segment sums; invariant: 0 at entry

__device__ __forceinline__ float silu(float v) { return v / (1.0f + expf(-v)); }

// =================== K1: streaming segment-sum (unchanged) ====================
__global__ void __launch_bounds__(256) reduce_kernel(
    const float4* __restrict__ x4, const int* __restrict__ cu)
{
    const int tid = threadIdx.x;
    const int t0  = blockIdx.x * ROWS_PER_BLK;

    __shared__ int scu[B_SEG + 1];
    if (tid <= B_SEG) scu[tid] = cu[tid];
    __syncthreads();

    const int t1 = t0 + ROWS_PER_BLK - 1;
    int s0 = 0; while (s0 < B_SEG - 1 && t0 >= scu[s0 + 1]) s0++;
    int s1 = 0; while (s1 < B_SEG - 1 && t1 >= scu[s1 + 1]) s1++;

    const float4* xp = x4 + (size_t)t0 * C4 + tid;

    if (s0 == s1) {
        float4 a[8];
        #pragma unroll
        for (int i = 0; i < 8; i++) a[i] = make_float4(0.f,0.f,0.f,0.f);
        #pragma unroll
        for (int r = 0; r < ROWS_PER_BLK; r += 8) {
            #pragma unroll
            for (int u = 0; u < 8; u++) {
                float4 v = __ldcs(&xp[(r + u) * C4]);
                a[u].x += v.x; a[u].y += v.y; a[u].z += v.z; a[u].w += v.w;
            }
        }
        #pragma unroll
        for (int s = 4; s > 0; s >>= 1)
            #pragma unroll
            for (int i = 0; i < s; i++) {
                a[i].x += a[i+s].x; a[i].y += a[i+s].y;
                a[i].z += a[i+s].z; a[i].w += a[i+s].w;
            }
        float* dst = g_accum + s0 * C_COLS + tid * 4;
        atomicAdd(dst + 0, a[0].x); atomicAdd(dst + 1, a[0].y);
        atomicAdd(dst + 2, a[0].z); atomicAdd(dst + 3, a[0].w);
    } else {
        float4 a = make_float4(0.f,0.f,0.f,0.f);
        int seg = s0;
        int nxt = (seg < B_SEG - 1) ? scu[seg + 1] : 0x7fffffff;
        for (int r = 0; r < ROWS_PER_BLK; r++) {
            int t = t0 + r;
            if (t >= nxt) {
                float* dst = g_accum + seg * C_COLS + tid * 4;
                atomicAdd(dst + 0, a.x); atomicAdd(dst + 1, a.y);
                atomicAdd(dst + 2, a.z); atomicAdd(dst + 3, a.w);
                a = make_float4(0.f,0.f,0.f,0.f);
                while (seg < B_SEG - 1 && t >= scu[seg + 1]) seg++;
                nxt = (seg < B_SEG - 1) ? scu[seg + 1] : 0x7fffffff;
            }
            float4 v = __ldcs(&xp[r * C4]);
            a.x += v.x; a.y += v.y; a.z += v.z; a.w += v.w;
        }
        float* dst = g_accum + seg * C_COLS + tid * 4;
        atomicAdd(dst + 0, a.x); atomicAdd(dst + 1, a.y);
        atomicAdd(dst + 2, a.z); atomicAdd(dst + 3, a.w);
    }
}

// =================== K2: whole MLP, 1 block/batch row, 1024 threads ===========
// Weight loads explicitly batched 8-deep into register arrays (MLP_eff ~ 8).
__global__ void __launch_bounds__(1024) mlp_kernel(
    const int* __restrict__ cu,
    const float* __restrict__ w1, const float* __restrict__ b1,
    const float* __restrict__ w2, const float* __restrict__ b2,
    const float* __restrict__ w3, const float* __restrict__ b3,
    const float* __restrict__ w4, const float* __restrict__ b4,
    const float* __restrict__ w5, const float* __restrict__ b5,
    float* __restrict__ out)
{
    __shared__ float  pooled[D_DIM];
    __shared__ float  h1[1024];
    __shared__ float  h2[256];
    __shared__ float  h3[512];
    __shared__ float  h4[128];
    __shared__ float4 red[1024];         // 16 KB: per-layer k-slice partials
    __shared__ float  l0[128], l1[128];

    const int tid = threadIdx.x;
    const int b   = blockIdx.x;

    // ---- pooled mean over heads ---------------------------------------------
    if (tid < D_DIM) {
        float s = 0.f;
        #pragma unroll
        for (int h = 0; h < H_HEADS; h++)
            s += __ldcg(&g_accum[b * C_COLS + h * D_DIM + tid]);
        int cnt = cu[b + 1] - cu[b];
        if (cnt < 1) cnt = 1;
        pooled[tid] = s / ((float)cnt * (float)H_HEADS);
    }
    __syncthreads();

    float4 wv[8];

    // ---- L1: 128 -> 1024, silu.  256 jq x 4 slices (k=32 each) ---------------
    {
        const int jq = tid & 255, slice = tid >> 8;
        const int k0 = slice * 32;
        const float* wp = &w1[k0 * 1024 + jq * 4];
        float4 acc = make_float4(0.f,0.f,0.f,0.f);
        #pragma unroll
        for (int kb = 0; kb < 32; kb += 8) {
            #pragma unroll
            for (int u = 0; u < 8; u++)
                wv[u] = *(const float4*)&wp[(kb + u) * 1024];
            #pragma unroll
            for (int u = 0; u < 8; u++) {
                float xv = pooled[k0 + kb + u];
                acc.x += xv * wv[u].x; acc.y += xv * wv[u].y;
                acc.z += xv * wv[u].z; acc.w += xv * wv[u].w;
            }
        }
        red[slice * 256 + jq] = acc;
        __syncthreads();
        if (tid < 256) {
            float4 s = make_float4(0.f,0.f,0.f,0.f);
            #pragma unroll
            for (int sl = 0; sl < 4; sl++) {
                float4 v = red[sl * 256 + tid];
                s.x += v.x; s.y += v.y; s.z += v.z; s.w += v.w;
            }
            float4 bias = *(const float4*)&b1[tid * 4];
            h1[tid * 4 + 0] = silu(s.x + bias.x);
            h1[tid * 4 + 1] = silu(s.y + bias.y);
            h1[tid * 4 + 2] = silu(s.z + bias.z);
            h1[tid * 4 + 3] = silu(s.w + bias.w);
        }
        __syncthreads();
    }

    // ---- L2: 1024 -> 256, no act.  64 jq x 16 slices (k=64 each) -------------
    {
        const int jq = tid & 63, slice = tid >> 6;
        const int k0 = slice * 64;
        const float* wp = &w2[k0 * 256 + jq * 4];
        float4 acc = make_float4(0.f,0.f,0.f,0.f);
        #pragma unroll
        for (int kb = 0; kb < 64; kb += 8) {
            #pragma unroll
            for (int u = 0; u < 8; u++)
                wv[u] = *(const float4*)&wp[(kb + u) * 256];
            #pragma unroll
            for (int u = 0; u < 8; u++) {
                float xv = h1[k0 + kb + u];
                acc.x += xv * wv[u].x; acc.y += xv * wv[u].y;
                acc.z += xv * wv[u].z; acc.w += xv * wv[u].w;
            }
        }
        red[slice * 64 + jq] = acc;
        __syncthreads();
        if (tid < 64) {
            float4 s = make_float4(0.f,0.f,0.f,0.f);
            #pragma unroll
            for (int sl = 0; sl < 16; sl++) {
                float4 v = red[sl * 64 + tid];
                s.x += v.x; s.y += v.y; s.z += v.z; s.w += v.w;
            }
            float4 bias = *(const float4*)&b2[tid * 4];
            h2[tid * 4 + 0] = s.x + bias.x;
            h2[tid * 4 + 1] = s.y + bias.y;
            h2[tid * 4 + 2] = s.z + bias.z;
            h2[tid * 4 + 3] = s.w + bias.w;
        }
        __syncthreads();
    }

    // ---- L3: 256 -> 512, silu.  128 jq x 8 slices (k=32 each) ----------------
    {
        const int jq = tid & 127, slice = tid >> 7;
        const int k0 = slice * 32;
        const float* wp = &w3[k0 * 512 + jq * 4];
        float4 acc = make_float4(0.f,0.f,0.f,0.f);
        #pragma unroll
        for (int kb = 0; kb < 32; kb += 8) {
            #pragma unroll
            for (int u = 0; u < 8; u++)
                wv[u] = *(const float4*)&wp[(kb + u) * 512];
            #pragma unroll
            for (int u = 0; u < 8; u++) {
                float xv = h2[k0 + kb + u];
                acc.x += xv * wv[u].x; acc.y += xv * wv[u].y;
                acc.z += xv * wv[u].z; acc.w += xv * wv[u].w;
            }
        }
        red[slice * 128 + jq] = acc;
        __syncthreads();
        if (tid < 128) {
            float4 s = make_float4(0.f,0.f,0.f,0.f);
            #pragma unroll
            for (int sl = 0; sl < 8; sl++) {
                float4 v = red[sl * 128 + tid];
                s.x += v.x; s.y += v.y; s.z += v.z; s.w += v.w;
            }
            float4 bias = *(const float4*)&b3[tid * 4];
            h3[tid * 4 + 0] = silu(s.x + bias.x);
            h3[tid * 4 + 1] = silu(s.y + bias.y);
            h3[tid * 4 + 2] = silu(s.z + bias.z);
            h3[tid * 4 + 3] = silu(s.w + bias.w);
        }
        __syncthreads();
    }

    // ---- L4: 512 -> 128, silu.  32 jq x 32 slices (k=16 each) ----------------
    {
        const int jq = tid & 31, slice = tid >> 5;
        const int k0 = slice * 16;
        const float* wp = &w4[k0 * 128 + jq * 4];
        float4 acc = make_float4(0.f,0.f,0.f,0.f);
        #pragma unroll
        for (int kb = 0; kb < 16; kb += 8) {
            #pragma unroll
            for (int u = 0; u < 8; u++)
                wv[u] = *(const float4*)&wp[(kb + u) * 128];
            #pragma unroll
            for (int u = 0; u < 8; u++) {
                float xv = h3[k0 + kb + u];
                acc.x += xv * wv[u].x; acc.y += xv * wv[u].y;
                acc.z += xv * wv[u].z; acc.w += xv * wv[u].w;
            }
        }
        red[slice * 32 + jq] = acc;
        __syncthreads();
        if (tid < 32) {
            float4 s = make_float4(0.f,0.f,0.f,0.f);
            #pragma unroll
            for (int sl = 0; sl < 32; sl++) {
                float4 v = red[sl * 32 + tid];
                s.x += v.x; s.y += v.y; s.z += v.z; s.w += v.w;
            }
            float4 bias = *(const float4*)&b4[tid * 4];
            h4[tid * 4 + 0] = silu(s.x + bias.x);
            h4[tid * 4 + 1] = silu(s.y + bias.y);
            h4[tid * 4 + 2] = silu(s.z + bias.z);
            h4[tid * 4 + 3] = silu(s.w + bias.w);
        }
        __syncthreads();
    }

    // ---- L5: 128 -> 2, argmax, output -----------------------------------------
    if (tid < 128) {
        float v = h4[tid];
        l0[tid] = v * w5[tid * 2 + 0];
        l1[tid] = v * w5[tid * 2 + 1];
    }
    __syncthreads();
    #pragma unroll
    for (int stride = 64; stride > 0; stride >>= 1) {
        if (tid < stride) {
            l0[tid] += l0[tid + stride];
            l1[tid] += l1[tid + stride];
        }
        __syncthreads();
    }
    if (tid == 0) {
        float lg0 = l0[0] + b5[0];
        float lg1 = l1[0] + b5[1];
        float z = (lg1 > lg0) ? 1.0f : 0.0f;     // argmax; tie -> class 0
        #pragma unroll
        for (int h = 0; h < H_HEADS; h++)
            out[b * H_HEADS + h] = z;
    }

    // ---- restore accumulator invariant for next graph replay ------------------
    for (int i = tid; i < C_COLS; i += 1024)
        g_accum[b * C_COLS + i] = 0.f;
}

// ---------------- launch --------------------------------------------------------
extern "C" void kernel_launch(void* const* d_in, const int* in_sizes, int n_in,
                              void* d_out, int out_size)
{
    const float* x  = (const float*)d_in[0];
    const int*   cu = (const int*)  d_in[1];
    const float* w1 = (const float*)d_in[2];
    const float* b1 = (const float*)d_in[3];
    const float* w2 = (const float*)d_in[4];
    const float* b2 = (const float*)d_in[5];
    const float* w3 = (const float*)d_in[6];
    const float* b3 = (const float*)d_in[7];
    const float* w4 = (const float*)d_in[8];
    const float* b4 = (const float*)d_in[9];
    const float* w5 = (const float*)d_in[10];
    const float* b5 = (const float*)d_in[11];

    reduce_kernel<<<RBLK, 256>>>((const float4*)x, cu);
    mlp_kernel<<<B_SEG, 1024>>>(cu, w1, b1, w2, b2, w3, b3, w4, b4, w5, b5,
                                (float*)d_out);
}